// round 1
// baseline (speedup 1.0000x reference)
#include <cuda_runtime.h>
#include <cuda_bf16.h>

// Problem constants (fixed shapes from reference setup_inputs)
#define NPTS 8192
#define NCH  4
#define TPB  256
#define IPT  4                      // i-points per thread (register tiling)
#define JCHUNK 256                  // j-points per CTA chunk (held in smem)
#define IBLOCKS (NPTS / (TPB * IPT))   // 8
#define JCHUNKS (NPTS / JCHUNK)        // 32
#define NBLK (IBLOCKS * JCHUNKS)       // 256 CTAs

// Per-CTA partial sums (fixed order -> deterministic). No device allocation.
__device__ float g_partials[NBLK];

__global__ void __launch_bounds__(TPB)
ewald_pair_kernel(const float* __restrict__ pos, const float* __restrict__ q) {
    __shared__ float sx[JCHUNK], sy[JCHUNK], sz[JCHUNK];
    __shared__ float sq0[JCHUNK], sq1[JCHUNK], sq2[JCHUNK], sq3[JCHUNK];

    const int t  = threadIdx.x;
    const int ib = blockIdx.x / JCHUNKS;   // which i-block
    const int jc = blockIdx.x % JCHUNKS;   // which j-chunk

    // Cooperative load of this CTA's j-chunk into smem (SoA for broadcast reads)
    {
        const int j = jc * JCHUNK + t;
        sx[t]  = pos[3 * j + 0];
        sy[t]  = pos[3 * j + 1];
        sz[t]  = pos[3 * j + 2];
        sq0[t] = q[4 * j + 0];
        sq1[t] = q[4 * j + 1];
        sq2[t] = q[4 * j + 2];
        sq3[t] = q[4 * j + 3];
    }
    __syncthreads();

    // Register-resident i points: IPT per thread
    float xi[IPT], yi[IPT], zi[IPT];
    float a0[IPT], a1[IPT], a2[IPT], a3[IPT];
    float acc[IPT];
#pragma unroll
    for (int k = 0; k < IPT; k++) {
        const int i = ib * (TPB * IPT) + k * TPB + t;
        xi[k] = pos[3 * i + 0];
        yi[k] = pos[3 * i + 1];
        zi[k] = pos[3 * i + 2];
        a0[k] = q[4 * i + 0];
        a1[k] = q[4 * i + 1];
        a2[k] = q[4 * i + 2];
        a3[k] = q[4 * i + 3];
        acc[k] = 0.0f;
    }

    const float INV_SQRT2 = 0.70710678118654752f;

#pragma unroll 2
    for (int jj = 0; jj < JCHUNK; jj++) {
        const float xj = sx[jj], yj = sy[jj], zj = sz[jj];
        const float b0 = sq0[jj], b1 = sq1[jj], b2 = sq2[jj], b3 = sq3[jj];
#pragma unroll
        for (int k = 0; k < IPT; k++) {
            const float dx = xj - xi[k];
            const float dy = yj - yi[k];
            const float dz = zj - zi[k];
            float r2 = fmaf(dx, dx, fmaf(dy, dy, dz * dz));
            float r  = sqrtf(r2);
            // diagonal: r=0 -> erf(0)=0 -> term exactly 0 (matches reference)
            float e    = erff(r * INV_SQRT2);
            float kern = e * __fdividef(1.0f, r + 1e-6f);
            float qd   = fmaf(a0[k], b0, fmaf(a1[k], b1, fmaf(a2[k], b2, a3[k] * b3)));
            acc[k]     = fmaf(qd, kern, acc[k]);
        }
    }

    // Deterministic in-block reduction
    float s = (acc[0] + acc[1]) + (acc[2] + acc[3]);
#pragma unroll
    for (int o = 16; o > 0; o >>= 1)
        s += __shfl_down_sync(0xffffffffu, s, o);

    __shared__ float red[TPB / 32];
    if ((t & 31) == 0) red[t >> 5] = s;
    __syncthreads();
    if (t < TPB / 32) {
        s = red[t];
#pragma unroll
        for (int o = (TPB / 64); o > 0; o >>= 1)
            s += __shfl_down_sync(0x000000ffu, s, o);
        if (t == 0) g_partials[blockIdx.x] = s;
    }
}

// Single-block final reduction (fixed order, fp64 accumulation) + self term.
__global__ void __launch_bounds__(TPB)
ewald_reduce_kernel(const float* __restrict__ q, float* __restrict__ out) {
    const int t = threadIdx.x;

    double s = 0.0;
    for (int i = t; i < NBLK; i += TPB) s += (double)g_partials[i];

    double ss = 0.0;
    for (int i = t; i < NPTS * NCH; i += TPB) {
        float v = q[i];
        ss += (double)v * (double)v;
    }

    __shared__ double rs[TPB];
    __shared__ double rss[TPB];
    rs[t] = s;
    rss[t] = ss;
    __syncthreads();
#pragma unroll
    for (int o = TPB / 2; o > 0; o >>= 1) {
        if (t < o) {
            rs[t]  += rs[t + o];
            rss[t] += rss[t + o];
        }
        __syncthreads();
    }
    if (t == 0) {
        // pair sum / (2*pi) / 2 = * 1/(4*pi); self: * 1/(sigma*(2*pi)^1.5)
        const double INV_4PI    = 0.07957747154594767;
        const double SELF_COEF  = 0.06349363593424097;  // 1/(2*pi)^{1.5}
        out[0] = (float)(rs[0] * INV_4PI + rss[0] * SELF_COEF);
    }
}

extern "C" void kernel_launch(void* const* d_in, const int* in_sizes, int n_in,
                              void* d_out, int out_size) {
    const float* pos = (const float*)d_in[0];   // [8192,3] fp32
    const float* q   = (const float*)d_in[1];   // [8192,4] fp32
    float* out = (float*)d_out;                 // [1] fp32

    ewald_pair_kernel<<<NBLK, TPB>>>(pos, q);
    ewald_reduce_kernel<<<1, TPB>>>(q, out);
}

// round 2
// speedup vs baseline: 1.8353x; 1.8353x over previous
#include <cuda_runtime.h>
#include <cuda_bf16.h>

// Problem constants (fixed shapes from reference setup_inputs)
#define NPTS 8192
#define NCH  4
#define TPB  128
#define IPT  4                         // i-points per thread (register tiling)
#define JCHUNK 128                     // j-points per CTA chunk (in smem)
#define IBLOCKS (NPTS / (TPB * IPT))   // 16
#define JCHUNKS (NPTS / JCHUNK)        // 64
#define NBLK (IBLOCKS * JCHUNKS)       // 1024 CTAs (fine-grained for balance)

// Per-CTA partial sums (fixed order -> deterministic). No device allocation.
__device__ float g_partials[NBLK];

// Abramowitz-Stegun 7.1.26 constants, with the x = r/sqrt(2) scale folded in,
// and poly coefficients NEGATED so Horner yields -poly directly.
#define P_OVER_SQRT2   0.23170396f     // 0.3275911 / sqrt(2)
#define NA1  (-0.254829592f)
#define NA2  ( 0.284496736f)
#define NA3  (-1.421413741f)
#define NA4  ( 1.453152027f)
#define NA5  (-1.061405429f)
#define NEG_HALF_LOG2E (-0.7213475204444817f)  // -0.5 * log2(e)

__global__ void __launch_bounds__(TPB)
ewald_pair_kernel(const float* __restrict__ pos, const float* __restrict__ q) {
    __shared__ float sx[JCHUNK], sy[JCHUNK], sz[JCHUNK];
    __shared__ float sq0[JCHUNK], sq1[JCHUNK], sq2[JCHUNK], sq3[JCHUNK];

    const int t  = threadIdx.x;
    const int ib = blockIdx.x / JCHUNKS;   // which i-block
    const int jc = blockIdx.x % JCHUNKS;   // which j-chunk

    // Cooperative load of this CTA's j-chunk into smem (SoA, broadcast reads)
    {
        const int j = jc * JCHUNK + t;
        sx[t]  = pos[3 * j + 0];
        sy[t]  = pos[3 * j + 1];
        sz[t]  = pos[3 * j + 2];
        sq0[t] = q[4 * j + 0];
        sq1[t] = q[4 * j + 1];
        sq2[t] = q[4 * j + 2];
        sq3[t] = q[4 * j + 3];
    }
    __syncthreads();

    // Register-resident i points: IPT per thread
    float xi[IPT], yi[IPT], zi[IPT];
    float a0[IPT], a1[IPT], a2[IPT], a3[IPT];
    float acc[IPT];
#pragma unroll
    for (int k = 0; k < IPT; k++) {
        const int i = ib * (TPB * IPT) + k * TPB + t;
        xi[k] = pos[3 * i + 0];
        yi[k] = pos[3 * i + 1];
        zi[k] = pos[3 * i + 2];
        a0[k] = q[4 * i + 0];
        a1[k] = q[4 * i + 1];
        a2[k] = q[4 * i + 2];
        a3[k] = q[4 * i + 3];
        acc[k] = 0.0f;
    }

#pragma unroll 2
    for (int jj = 0; jj < JCHUNK; jj++) {
        const float xj = sx[jj], yj = sy[jj], zj = sz[jj];
        const float b0 = sq0[jj], b1 = sq1[jj], b2 = sq2[jj], b3 = sq3[jj];
#pragma unroll
        for (int k = 0; k < IPT; k++) {
            const float dx = xj - xi[k];
            const float dy = yj - yi[k];
            const float dz = zj - zi[k];
            const float r2 = fmaf(dx, dx, fmaf(dy, dy, dz * dz));

            const float rinv = rsqrtf(r2);            // MUFU.RSQ (inf at r2=0)
            const float r    = r2 * rinv;             // NaN at diagonal; masked below

            // erf(r/sqrt(2)) via A&S 7.1.26: 1 RCP + 1 EX2 + 6 fma-ops
            const float d    = fmaf(P_OVER_SQRT2, r, 1.0f);
            const float tt   = __fdividef(1.0f, d);   // MUFU.RCP
            float pn = fmaf(NA5, tt, NA4);
            pn = fmaf(pn, tt, NA3);
            pn = fmaf(pn, tt, NA2);
            pn = fmaf(pn, tt, NA1);
            pn = pn * tt;                              // = -poly(t)
            const float expt = exp2f(r2 * NEG_HALF_LOG2E);  // MUFU.EX2
            const float erfv = fmaf(pn, expt, 1.0f);

            const float kern0 = erfv * rinv;
            const float kern  = (r2 > 0.0f) ? kern0 : 0.0f;  // exact-zero diagonal

            const float qd = fmaf(a0[k], b0, fmaf(a1[k], b1, fmaf(a2[k], b2, a3[k] * b3)));
            acc[k] = fmaf(qd, kern, acc[k]);
        }
    }

    // Deterministic in-block reduction (128 threads = 4 warps)
    float s = (acc[0] + acc[1]) + (acc[2] + acc[3]);
#pragma unroll
    for (int o = 16; o > 0; o >>= 1)
        s += __shfl_down_sync(0xffffffffu, s, o);

    __shared__ float red[TPB / 32];
    if ((t & 31) == 0) red[t >> 5] = s;
    __syncthreads();
    if (t == 0) {
        g_partials[blockIdx.x] = (red[0] + red[1]) + (red[2] + red[3]);
    }
}

// Single-block final reduction (fixed order) + self term.
#define RTPB 256
__global__ void __launch_bounds__(RTPB)
ewald_reduce_kernel(const float* __restrict__ q, float* __restrict__ out) {
    const int t = threadIdx.x;

    // Pair-sum partials: 1024 / 256 = 4 each (fp64, cheap)
    double s = 0.0;
#pragma unroll
    for (int u = 0; u < NBLK / RTPB; u++)
        s += (double)g_partials[u * RTPB + t];

    // sum(q*q): 32768 / 256 = 128 each, fp32 with 4 independent accumulators
    float ss0 = 0.0f, ss1 = 0.0f, ss2 = 0.0f, ss3 = 0.0f;
    const float4* q4 = (const float4*)q;   // 8192 float4's
#pragma unroll 4
    for (int u = 0; u < (NPTS * NCH) / (4 * RTPB); u++) {
        const float4 v = q4[u * RTPB + t];
        ss0 = fmaf(v.x, v.x, ss0);
        ss1 = fmaf(v.y, v.y, ss1);
        ss2 = fmaf(v.z, v.z, ss2);
        ss3 = fmaf(v.w, v.w, ss3);
    }
    double ss = (double)((ss0 + ss1) + (ss2 + ss3));

    __shared__ double rs[RTPB];
    __shared__ double rss[RTPB];
    rs[t] = s;
    rss[t] = ss;
    __syncthreads();
#pragma unroll
    for (int o = RTPB / 2; o > 0; o >>= 1) {
        if (t < o) {
            rs[t]  += rs[t + o];
            rss[t] += rss[t + o];
        }
        __syncthreads();
    }
    if (t == 0) {
        // pair sum / (2*pi) / 2 = * 1/(4*pi); self: * 1/(sigma*(2*pi)^1.5)
        const double INV_4PI   = 0.07957747154594767;
        const double SELF_COEF = 0.06349363593424097;  // 1/(2*pi)^{1.5}
        out[0] = (float)(rs[0] * INV_4PI + rss[0] * SELF_COEF);
    }
}

extern "C" void kernel_launch(void* const* d_in, const int* in_sizes, int n_in,
                              void* d_out, int out_size) {
    const float* pos = (const float*)d_in[0];   // [8192,3] fp32
    const float* q   = (const float*)d_in[1];   // [8192,4] fp32
    float* out = (float*)d_out;                 // [1] fp32

    ewald_pair_kernel<<<NBLK, TPB>>>(pos, q);
    ewald_reduce_kernel<<<1, RTPB>>>(q, out);
}

// round 3
// speedup vs baseline: 2.1259x; 1.1583x over previous
#include <cuda_runtime.h>
#include <cuda_bf16.h>

// Fixed shapes from reference setup_inputs
#define NPTS 8192
#define NCH  4
#define TPB  256
#define IPT  2                       // i-points per thread
#define TILE 512                     // square tile edge (= TPB*IPT)
#define NTILES (NPTS / TILE)         // 16
#define NBLK (NTILES * (NTILES + 1) / 2)   // 136 triangular tiles, one wave

// Per-CTA partial sums (fixed order -> deterministic). No device allocation.
__device__ float g_partials[NBLK];

// Abramowitz-Stegun 7.1.26, x = r/sqrt(2) scale folded in, coefficients negated.
#define P_OVER_SQRT2   0.23170396f   // 0.3275911 / sqrt(2)
#define NA1  (-0.254829592f)
#define NA2  ( 0.284496736f)
#define NA3  (-1.421413741f)
#define NA4  ( 1.453152027f)
#define NA5  (-1.061405429f)
#define NEG_HALF_LOG2E (-0.7213475204444817f)   // -0.5 * log2(e)
// self-term coefficient relative to the pair-sum scale:
// SELF_COEF / INV_4PI = 4*pi / (2*pi)^{1.5} = 2/sqrt(2*pi)
#define SELF_RATIO 0.7978845608028654f

__global__ void __launch_bounds__(TPB)
ewald_pair_kernel(const float* __restrict__ pos, const float* __restrict__ q) {
    __shared__ float sx[TILE], sy[TILE], sz[TILE];
    __shared__ float sq0[TILE], sq1[TILE], sq2[TILE], sq3[TILE];

    const int t = threadIdx.x;

    // Map linear block id -> triangular tile (I, J), J >= I
    int I = 0, rem = blockIdx.x;
    while (rem >= NTILES - I) { rem -= NTILES - I; I++; }
    const int J = I + rem;
    const bool diag = (I == J);

    // Cooperative load of j-tile (TILE=512 rows, 256 threads -> 2 each)
#pragma unroll
    for (int u = 0; u < TILE / TPB; u++) {
        const int jj = u * TPB + t;
        const int j  = J * TILE + jj;
        sx[jj]  = pos[3 * j + 0];
        sy[jj]  = pos[3 * j + 1];
        sz[jj]  = pos[3 * j + 2];
        sq0[jj] = q[4 * j + 0];
        sq1[jj] = q[4 * j + 1];
        sq2[jj] = q[4 * j + 2];
        sq3[jj] = q[4 * j + 3];
    }
    __syncthreads();

    // Register-resident i points
    float xi[IPT], yi[IPT], zi[IPT];
    float a0[IPT], a1[IPT], a2[IPT], a3[IPT];
    float acc[IPT];
    float qq = 0.0f;   // self-term contribution (diagonal CTAs only)
#pragma unroll
    for (int k = 0; k < IPT; k++) {
        const int i = I * TILE + k * TPB + t;
        xi[k] = pos[3 * i + 0];
        yi[k] = pos[3 * i + 1];
        zi[k] = pos[3 * i + 2];
        a0[k] = q[4 * i + 0];
        a1[k] = q[4 * i + 1];
        a2[k] = q[4 * i + 2];
        a3[k] = q[4 * i + 3];
        acc[k] = 0.0f;
        qq += fmaf(a0[k], a0[k], fmaf(a1[k], a1[k],
              fmaf(a2[k], a2[k], a3[k] * a3[k])));
    }

#pragma unroll 2
    for (int jj = 0; jj < TILE; jj++) {
        const float xj = sx[jj], yj = sy[jj], zj = sz[jj];
        const float b0 = sq0[jj], b1 = sq1[jj], b2 = sq2[jj], b3 = sq3[jj];
#pragma unroll
        for (int k = 0; k < IPT; k++) {
            const float dx = xj - xi[k];
            const float dy = yj - yi[k];
            const float dz = zj - zi[k];
            const float r2 = fmaf(dx, dx, fmaf(dy, dy, dz * dz));

            const float rinv = rsqrtf(r2);           // MUFU.RSQ (inf on diagonal)
            const float r    = r2 * rinv;            // NaN on diagonal; masked below

            // erf(r/sqrt(2)) via A&S 7.1.26
            const float d  = fmaf(P_OVER_SQRT2, r, 1.0f);
            const float tt = __fdividef(1.0f, d);    // MUFU.RCP
            float pn = fmaf(NA5, tt, NA4);
            pn = fmaf(pn, tt, NA3);
            pn = fmaf(pn, tt, NA2);
            pn = fmaf(pn, tt, NA1);
            pn = pn * tt;                            // = -poly(t)
            const float expt = exp2f(r2 * NEG_HALF_LOG2E);   // MUFU.EX2
            const float erfv = fmaf(pn, expt, 1.0f);

            const float kern0 = erfv * rinv;
            const float kern  = (r2 > 0.0f) ? kern0 : 0.0f;  // exact zero diagonal

            const float qd = fmaf(a0[k], b0, fmaf(a1[k], b1,
                             fmaf(a2[k], b2, a3[k] * b3)));
            acc[k] = fmaf(qd, kern, acc[k]);
        }
    }

    // Per-thread value: weight off-diagonal tiles by 2; diagonal tiles carry
    // the self term (scaled so one global INV_4PI factor applies at the end).
    const float w = diag ? 1.0f : 2.0f;
    float s = w * (acc[0] + acc[1]);
    if (diag) s = fmaf(SELF_RATIO, qq, s);

    // Deterministic in-block reduction (256 threads = 8 warps)
#pragma unroll
    for (int o = 16; o > 0; o >>= 1)
        s += __shfl_down_sync(0xffffffffu, s, o);

    __shared__ float red[TPB / 32];
    if ((t & 31) == 0) red[t >> 5] = s;
    __syncthreads();
    if (t == 0) {
        float r0 = ((red[0] + red[1]) + (red[2] + red[3]))
                 + ((red[4] + red[5]) + (red[6] + red[7]));
        g_partials[blockIdx.x] = r0;
    }
}

// Tiny final reduction: 136 floats, one warp, fp64, fixed order.
__global__ void __launch_bounds__(32)
ewald_reduce_kernel(float* __restrict__ out) {
    const int t = threadIdx.x;
    double s = 0.0;
    for (int i = t; i < NBLK; i += 32) s += (double)g_partials[i];
#pragma unroll
    for (int o = 16; o > 0; o >>= 1) {
        double v = __shfl_down_sync(0xffffffffu, s, o);
        s += v;
    }
    if (t == 0) {
        const double INV_4PI = 0.07957747154594767;  // 1/(4*pi)
        out[0] = (float)(s * INV_4PI);
    }
}

extern "C" void kernel_launch(void* const* d_in, const int* in_sizes, int n_in,
                              void* d_out, int out_size) {
    const float* pos = (const float*)d_in[0];   // [8192,3] fp32
    const float* q   = (const float*)d_in[1];   // [8192,4] fp32
    float* out = (float*)d_out;                 // [1] fp32

    ewald_pair_kernel<<<NBLK, TPB>>>(pos, q);
    ewald_reduce_kernel<<<1, 32>>>(out);
}

// round 4
// speedup vs baseline: 3.4601x; 1.6276x over previous
#include <cuda_runtime.h>
#include <cuda_bf16.h>

// Fixed shapes from reference setup_inputs
#define NPTS 8192
#define TPB  256
#define TILE 512                     // i-tile edge (= TPB * 2 packed i per thread)
#define JC   128                     // j-chunk per CTA (TILE/4)
#define NTILES (NPTS / TILE)         // 16
#define NTRI (NTILES * (NTILES + 1) / 2)   // 136 triangular tiles
#define NBLK (NTRI * 4)              // 544 CTAs

typedef unsigned long long u64;

__device__ float g_partials[NBLK];
__device__ unsigned int g_count;     // zero at load; self-reset each launch

// A&S 7.1.26, x = r/sqrt(2) folded, coefficients negated
#define P_OVER_SQRT2   0.23170396f
#define NA1c  (-0.254829592f)
#define NA2c  ( 0.284496736f)
#define NA3c  (-1.421413741f)
#define NA4c  ( 1.453152027f)
#define NA5c  (-1.061405429f)
#define NEG_HALF_LOG2E (-0.7213475204444817f)
#define SELF_RATIO 0.7978845608028654f   // (1/(2pi)^1.5) / (1/(4pi))

// ---- packed f32x2 helpers (Blackwell) ----
__device__ __forceinline__ u64 ffma2(u64 a, u64 b, u64 c) {
    u64 d; asm("fma.rn.f32x2 %0,%1,%2,%3;" : "=l"(d) : "l"(a), "l"(b), "l"(c)); return d;
}
__device__ __forceinline__ u64 fmul2(u64 a, u64 b) {
    u64 d; asm("mul.rn.f32x2 %0,%1,%2;" : "=l"(d) : "l"(a), "l"(b)); return d;
}
__device__ __forceinline__ u64 fadd2(u64 a, u64 b) {
    u64 d; asm("add.rn.f32x2 %0,%1,%2;" : "=l"(d) : "l"(a), "l"(b)); return d;
}
__device__ __forceinline__ u64 pack2(float lo, float hi) {
    u64 d; asm("mov.b64 %0,{%1,%2};" : "=l"(d) : "f"(lo), "f"(hi)); return d;
}
__device__ __forceinline__ float2 unpack2(u64 v) {
    float2 f; asm("mov.b64 {%0,%1},%2;" : "=f"(f.x), "=f"(f.y) : "l"(v)); return f;
}
__device__ __forceinline__ u64 rsq2(u64 a) {
    u64 r;
    asm("{\n\t.reg .f32 lo,hi,rl,rh;\n\t"
        "mov.b64 {lo,hi},%1;\n\t"
        "rsqrt.approx.f32 rl,lo;\n\t"
        "rsqrt.approx.f32 rh,hi;\n\t"
        "mov.b64 %0,{rl,rh};\n\t}" : "=l"(r) : "l"(a));
    return r;
}
__device__ __forceinline__ u64 rcp2(u64 a) {
    u64 r;
    asm("{\n\t.reg .f32 lo,hi,rl,rh;\n\t"
        "mov.b64 {lo,hi},%1;\n\t"
        "rcp.approx.f32 rl,lo;\n\t"
        "rcp.approx.f32 rh,hi;\n\t"
        "mov.b64 %0,{rl,rh};\n\t}" : "=l"(r) : "l"(a));
    return r;
}
__device__ __forceinline__ u64 ex22(u64 a) {
    u64 r;
    asm("{\n\t.reg .f32 lo,hi,rl,rh;\n\t"
        "mov.b64 {lo,hi},%1;\n\t"
        "ex2.approx.f32 rl,lo;\n\t"
        "ex2.approx.f32 rh,hi;\n\t"
        "mov.b64 %0,{rl,rh};\n\t}" : "=l"(r) : "l"(a));
    return r;
}

__global__ void __launch_bounds__(TPB, 4)
ewald_pair_kernel(const float* __restrict__ pos, const float* __restrict__ q,
                  float* __restrict__ out) {
    // j-chunk in smem, each value duplicated into both f32x2 halves
    __shared__ u64 sxj[JC], syj[JC], szj[JC];
    __shared__ u64 sb0[JC], sb1[JC], sb2[JC], sb3[JC];

    const int t = threadIdx.x;

    // block -> (tile, chunk) -> (I, J)
    const int tile  = blockIdx.x >> 2;
    const int chunk = blockIdx.x & 3;
    int I = 0, rem = tile;
    while (rem >= NTILES - I) { rem -= NTILES - I; I++; }
    const int J = I + rem;
    const bool diag = (I == J);

    // Fill j-chunk (JC=128 rows; threads 0..127)
    if (t < JC) {
        const int j = J * TILE + chunk * JC + t;
        float v;
        v = pos[3 * j + 0]; sxj[t] = pack2(v, v);
        v = pos[3 * j + 1]; syj[t] = pack2(v, v);
        v = pos[3 * j + 2]; szj[t] = pack2(v, v);
        v = q[4 * j + 0];   sb0[t] = pack2(v, v);
        v = q[4 * j + 1];   sb1[t] = pack2(v, v);
        v = q[4 * j + 2];   sb2[t] = pack2(v, v);
        v = q[4 * j + 3];   sb3[t] = pack2(v, v);
    }
    __syncthreads();

    // i pair for this thread: (i0, i0+1)
    const int i0 = I * TILE + 2 * t;
    const u64 nxi = pack2(-pos[3 * i0 + 0], -pos[3 * i0 + 3]);
    const u64 nyi = pack2(-pos[3 * i0 + 1], -pos[3 * i0 + 4]);
    const u64 nzi = pack2(-pos[3 * i0 + 2], -pos[3 * i0 + 5]);
    const float a0x = q[4 * i0 + 0], a0y = q[4 * i0 + 4];
    const float a1x = q[4 * i0 + 1], a1y = q[4 * i0 + 5];
    const float a2x = q[4 * i0 + 2], a2y = q[4 * i0 + 6];
    const float a3x = q[4 * i0 + 3], a3y = q[4 * i0 + 7];
    const u64 A0 = pack2(a0x, a0y), A1 = pack2(a1x, a1y);
    const u64 A2 = pack2(a2x, a2y), A3 = pack2(a3x, a3y);

    // packed constants
    const u64 P2   = pack2(P_OVER_SQRT2, P_OVER_SQRT2);
    const u64 ONE2 = pack2(1.0f, 1.0f);
    const u64 N5   = pack2(NA5c, NA5c), N4 = pack2(NA4c, NA4c);
    const u64 N3   = pack2(NA3c, NA3c), N2 = pack2(NA2c, NA2c);
    const u64 N1   = pack2(NA1c, NA1c);
    const u64 NHL  = pack2(NEG_HALF_LOG2E, NEG_HALF_LOG2E);

    u64 acc = 0ull;   // packed zero accumulator

    if (!diag) {
#pragma unroll 4
        for (int jj = 0; jj < JC; jj++) {
            const u64 dx = fadd2(sxj[jj], nxi);
            const u64 dy = fadd2(syj[jj], nyi);
            const u64 dz = fadd2(szj[jj], nzi);
            const u64 r2 = ffma2(dx, dx, ffma2(dy, dy, fmul2(dz, dz)));
            const u64 rinv = rsq2(r2);
            const u64 r  = fmul2(r2, rinv);
            const u64 dd = ffma2(P2, r, ONE2);
            const u64 tt = rcp2(dd);
            u64 pn = ffma2(N5, tt, N4);
            pn = ffma2(pn, tt, N3);
            pn = ffma2(pn, tt, N2);
            pn = ffma2(pn, tt, N1);
            pn = fmul2(pn, tt);
            const u64 ex   = ex22(fmul2(r2, NHL));
            const u64 erfv = ffma2(pn, ex, ONE2);
            const u64 kern = fmul2(erfv, rinv);
            const u64 qd = ffma2(A0, sb0[jj], ffma2(A1, sb1[jj],
                           ffma2(A2, sb2[jj], fmul2(A3, sb3[jj]))));
            acc = ffma2(qd, kern, acc);
        }
    } else {
#pragma unroll 4
        for (int jj = 0; jj < JC; jj++) {
            const u64 dx = fadd2(sxj[jj], nxi);
            const u64 dy = fadd2(syj[jj], nyi);
            const u64 dz = fadd2(szj[jj], nzi);
            const u64 r2 = ffma2(dx, dx, ffma2(dy, dy, fmul2(dz, dz)));
            const u64 rinv = rsq2(r2);
            const u64 r  = fmul2(r2, rinv);
            const u64 dd = ffma2(P2, r, ONE2);
            const u64 tt = rcp2(dd);
            u64 pn = ffma2(N5, tt, N4);
            pn = ffma2(pn, tt, N3);
            pn = ffma2(pn, tt, N2);
            pn = ffma2(pn, tt, N1);
            pn = fmul2(pn, tt);
            const u64 ex   = ex22(fmul2(r2, NHL));
            const u64 erfv = ffma2(pn, ex, ONE2);
            u64 kern = fmul2(erfv, rinv);
            // exact-zero diagonal (r2 == 0 -> kern NaN -> select 0)
            {
                float2 kf  = unpack2(kern);
                float2 rf  = unpack2(r2);
                kf.x = (rf.x > 0.0f) ? kf.x : 0.0f;
                kf.y = (rf.y > 0.0f) ? kf.y : 0.0f;
                kern = pack2(kf.x, kf.y);
            }
            const u64 qd = ffma2(A0, sb0[jj], ffma2(A1, sb1[jj],
                           ffma2(A2, sb2[jj], fmul2(A3, sb3[jj]))));
            acc = ffma2(qd, kern, acc);
        }
    }

    // thread value: off-diag tiles weighted 2x; self term on diag chunk 0
    float2 af = unpack2(acc);
    float s = af.x + af.y;
    if (!diag) s = s + s;
    else if (chunk == 0) {
        const float qq = fmaf(a0x, a0x, fmaf(a1x, a1x, fmaf(a2x, a2x, a3x * a3x)))
                       + fmaf(a0y, a0y, fmaf(a1y, a1y, fmaf(a2y, a2y, a3y * a3y)));
        s = fmaf(SELF_RATIO, qq, s);
    }

    // deterministic in-block reduction (8 warps)
#pragma unroll
    for (int o = 16; o > 0; o >>= 1)
        s += __shfl_down_sync(0xffffffffu, s, o);

    __shared__ float red[TPB / 32];
    if ((t & 31) == 0) red[t >> 5] = s;
    __syncthreads();

    __shared__ bool is_last;
    if (t == 0) {
        g_partials[blockIdx.x] = ((red[0] + red[1]) + (red[2] + red[3]))
                               + ((red[4] + red[5]) + (red[6] + red[7]));
        __threadfence();
        const unsigned int c = atomicAdd(&g_count, 1u);
        is_last = (c == NBLK - 1);
    }
    __syncthreads();

    // last CTA: fixed-order fp64 final reduction + scale
    if (is_last) {
        __threadfence();
        double d = (double)g_partials[t] + (double)g_partials[t + 256];
        if (t < NBLK - 512) d += (double)g_partials[t + 512];

        __shared__ double rs[TPB];
        rs[t] = d;
        __syncthreads();
#pragma unroll
        for (int o = TPB / 2; o > 0; o >>= 1) {
            if (t < o) rs[t] += rs[t + o];
            __syncthreads();
        }
        if (t == 0) {
            const double INV_4PI = 0.07957747154594767;
            out[0] = (float)(rs[0] * INV_4PI);
            g_count = 0;   // reset for next graph replay
        }
    }
}

extern "C" void kernel_launch(void* const* d_in, const int* in_sizes, int n_in,
                              void* d_out, int out_size) {
    const float* pos = (const float*)d_in[0];   // [8192,3] fp32
    const float* q   = (const float*)d_in[1];   // [8192,4] fp32
    float* out = (float*)d_out;                 // [1] fp32

    ewald_pair_kernel<<<NBLK, TPB>>>(pos, q, out);
}

// round 5
// speedup vs baseline: 3.5228x; 1.0181x over previous
#include <cuda_runtime.h>
#include <cuda_bf16.h>

// Fixed shapes from reference setup_inputs
#define NPTS 8192
#define TPB  256
#define TILE 512                     // i-tile edge (TPB * 2 packed i per thread)
#define JC   128                     // j-chunk per CTA
#define NTILES (NPTS / TILE)         // 16
#define NTRI (NTILES * (NTILES + 1) / 2)   // 136 triangular tiles
#define NBLK (NTRI * 4)              // 544 CTAs

typedef unsigned long long u64;

__device__ float g_partials[NBLK];
__device__ unsigned int g_count;     // zero at load; self-reset each launch

// A&S 7.1.26, x = r/sqrt(2) folded, coefficients negated
#define P_OVER_SQRT2   0.23170396f
#define NA1c  (-0.254829592f)
#define NA2c  ( 0.284496736f)
#define NA3c  (-1.421413741f)
#define NA4c  ( 1.453152027f)
#define NA5c  (-1.061405429f)
#define NEG_HALF_LOG2E (-0.7213475204444817f)
#define SELF_RATIO 0.7978845608028654f   // (1/(2pi)^1.5) / (1/(4pi))

// ---- packed f32x2 helpers ----
__device__ __forceinline__ u64 ffma2(u64 a, u64 b, u64 c) {
    u64 d; asm("fma.rn.f32x2 %0,%1,%2,%3;" : "=l"(d) : "l"(a), "l"(b), "l"(c)); return d;
}
__device__ __forceinline__ u64 fmul2(u64 a, u64 b) {
    u64 d; asm("mul.rn.f32x2 %0,%1,%2;" : "=l"(d) : "l"(a), "l"(b)); return d;
}
__device__ __forceinline__ u64 fadd2(u64 a, u64 b) {
    u64 d; asm("add.rn.f32x2 %0,%1,%2;" : "=l"(d) : "l"(a), "l"(b)); return d;
}
__device__ __forceinline__ u64 pack2(float lo, float hi) {
    u64 d; asm("mov.b64 %0,{%1,%2};" : "=l"(d) : "f"(lo), "f"(hi)); return d;
}
__device__ __forceinline__ float2 unpack2(u64 v) {
    float2 f; asm("mov.b64 {%0,%1},%2;" : "=f"(f.x), "=f"(f.y) : "l"(v)); return f;
}
__device__ __forceinline__ u64 rsq2(u64 a) {
    u64 r;
    asm("{\n\t.reg .f32 lo,hi,rl,rh;\n\t"
        "mov.b64 {lo,hi},%1;\n\t"
        "rsqrt.approx.f32 rl,lo;\n\t"
        "rsqrt.approx.f32 rh,hi;\n\t"
        "mov.b64 %0,{rl,rh};\n\t}" : "=l"(r) : "l"(a));
    return r;
}
__device__ __forceinline__ u64 rcp2(u64 a) {
    u64 r;
    asm("{\n\t.reg .f32 lo,hi,rl,rh;\n\t"
        "mov.b64 {lo,hi},%1;\n\t"
        "rcp.approx.f32 rl,lo;\n\t"
        "rcp.approx.f32 rh,hi;\n\t"
        "mov.b64 %0,{rl,rh};\n\t}" : "=l"(r) : "l"(a));
    return r;
}
__device__ __forceinline__ u64 ex22(u64 a) {
    u64 r;
    asm("{\n\t.reg .f32 lo,hi,rl,rh;\n\t"
        "mov.b64 {lo,hi},%1;\n\t"
        "ex2.approx.f32 rl,lo;\n\t"
        "ex2.approx.f32 rh,hi;\n\t"
        "mov.b64 %0,{rl,rh};\n\t}" : "=l"(r) : "l"(a));
    return r;
}

__global__ void __launch_bounds__(TPB, 4)
ewald_pair_kernel(const float* __restrict__ pos, const float* __restrict__ q,
                  float* __restrict__ out) {
    // j-chunk, SoA of duplicated-lane u64s, vector-loadable as ulonglong2:
    //   s_xy : {x, y} per row     s_zb0 : {z, b0} per row
    //   s_b12: {b1, b2} per row   s_b3  : {b3}
    __shared__ __align__(16) u64 s_xy [2 * JC];
    __shared__ __align__(16) u64 s_zb0[2 * JC];
    __shared__ __align__(16) u64 s_b12[2 * JC];
    __shared__ __align__(16) u64 s_b3 [JC];

    const int t = threadIdx.x;

    // block -> (tile, chunk) -> (I, J)
    const int tile  = blockIdx.x >> 2;
    const int chunk = blockIdx.x & 3;
    int I = 0, rem = tile;
    while (rem >= NTILES - I) { rem -= NTILES - I; I++; }
    const int J = I + rem;
    const bool diag = (I == J);

    const int jbase = J * TILE + chunk * JC;
    if (t < JC) {                 // warps 0-3: positions
        const int j = jbase + t;
        float v;
        v = pos[3 * j + 0]; s_xy [2 * t + 0] = pack2(v, v);
        v = pos[3 * j + 1]; s_xy [2 * t + 1] = pack2(v, v);
        v = pos[3 * j + 2]; s_zb0[2 * t + 0] = pack2(v, v);
    } else {                      // warps 4-7: charges
        const int tq = t - JC;
        const int j  = jbase + tq;
        float v;
        v = q[4 * j + 0]; s_zb0[2 * tq + 1] = pack2(v, v);
        v = q[4 * j + 1]; s_b12[2 * tq + 0] = pack2(v, v);
        v = q[4 * j + 2]; s_b12[2 * tq + 1] = pack2(v, v);
        v = q[4 * j + 3]; s_b3 [tq]         = pack2(v, v);
    }
    __syncthreads();

    // i pair for this thread: (i0, i0+1), negated for fadd2-based diffs
    const int i0 = I * TILE + 2 * t;
    const u64 nxi = pack2(-pos[3 * i0 + 0], -pos[3 * i0 + 3]);
    const u64 nyi = pack2(-pos[3 * i0 + 1], -pos[3 * i0 + 4]);
    const u64 nzi = pack2(-pos[3 * i0 + 2], -pos[3 * i0 + 5]);

    // packed constants
    const u64 P2   = pack2(P_OVER_SQRT2, P_OVER_SQRT2);
    const u64 ONE2 = pack2(1.0f, 1.0f);
    const u64 N5   = pack2(NA5c, NA5c), N4 = pack2(NA4c, NA4c);
    const u64 N3   = pack2(NA3c, NA3c), N2 = pack2(NA2c, NA2c);
    const u64 N1   = pack2(NA1c, NA1c);
    const u64 NHL  = pack2(NEG_HALF_LOG2E, NEG_HALF_LOG2E);

    // per-channel packed accumulators (4 independent chains)
    u64 acc0 = 0ull, acc1 = 0ull, acc2 = 0ull, acc3 = 0ull;

    const ulonglong2* v_xy  = (const ulonglong2*)s_xy;
    const ulonglong2* v_zb0 = (const ulonglong2*)s_zb0;
    const ulonglong2* v_b12 = (const ulonglong2*)s_b12;

    if (!diag) {
#pragma unroll 8
        for (int jj = 0; jj < JC; jj++) {
            const ulonglong2 xy = v_xy[jj];
            const ulonglong2 zb = v_zb0[jj];
            const u64 dx = fadd2(xy.x, nxi);
            const u64 dy = fadd2(xy.y, nyi);
            const u64 dz = fadd2(zb.x, nzi);
            const u64 r2 = ffma2(dx, dx, ffma2(dy, dy, fmul2(dz, dz)));
            const u64 rinv = rsq2(r2);
            const u64 r  = fmul2(r2, rinv);
            const u64 dd = ffma2(P2, r, ONE2);
            const u64 tt = rcp2(dd);
            u64 pn = ffma2(N5, tt, N4);
            pn = ffma2(pn, tt, N3);
            pn = ffma2(pn, tt, N2);
            pn = ffma2(pn, tt, N1);
            pn = fmul2(pn, tt);
            const u64 ex   = ex22(fmul2(r2, NHL));
            const u64 erfv = ffma2(pn, ex, ONE2);
            const u64 kern = fmul2(erfv, rinv);
            const ulonglong2 b12 = v_b12[jj];
            acc0 = ffma2(kern, zb.y,     acc0);
            acc1 = ffma2(kern, b12.x,    acc1);
            acc2 = ffma2(kern, b12.y,    acc2);
            acc3 = ffma2(kern, s_b3[jj], acc3);
        }
    } else {
#pragma unroll 8
        for (int jj = 0; jj < JC; jj++) {
            const ulonglong2 xy = v_xy[jj];
            const ulonglong2 zb = v_zb0[jj];
            const u64 dx = fadd2(xy.x, nxi);
            const u64 dy = fadd2(xy.y, nyi);
            const u64 dz = fadd2(zb.x, nzi);
            const u64 r2 = ffma2(dx, dx, ffma2(dy, dy, fmul2(dz, dz)));
            const u64 rinv = rsq2(r2);
            const u64 r  = fmul2(r2, rinv);
            const u64 dd = ffma2(P2, r, ONE2);
            const u64 tt = rcp2(dd);
            u64 pn = ffma2(N5, tt, N4);
            pn = ffma2(pn, tt, N3);
            pn = ffma2(pn, tt, N2);
            pn = ffma2(pn, tt, N1);
            pn = fmul2(pn, tt);
            const u64 ex   = ex22(fmul2(r2, NHL));
            const u64 erfv = ffma2(pn, ex, ONE2);
            u64 kern = fmul2(erfv, rinv);
            {   // exact-zero diagonal (r2 == 0 -> kern NaN -> select 0)
                float2 kf = unpack2(kern);
                float2 rf = unpack2(r2);
                kf.x = (rf.x > 0.0f) ? kf.x : 0.0f;
                kf.y = (rf.y > 0.0f) ? kf.y : 0.0f;
                kern = pack2(kf.x, kf.y);
            }
            const ulonglong2 b12 = v_b12[jj];
            acc0 = ffma2(kern, zb.y,     acc0);
            acc1 = ffma2(kern, b12.x,    acc1);
            acc2 = ffma2(kern, b12.y,    acc2);
            acc3 = ffma2(kern, s_b3[jj], acc3);
        }
    }

    // Reload i charges now (L1 hit) and dot with per-channel accumulators
    const float a0x = q[4 * i0 + 0], a0y = q[4 * i0 + 4];
    const float a1x = q[4 * i0 + 1], a1y = q[4 * i0 + 5];
    const float a2x = q[4 * i0 + 2], a2y = q[4 * i0 + 6];
    const float a3x = q[4 * i0 + 3], a3y = q[4 * i0 + 7];
    const float2 f0 = unpack2(acc0), f1 = unpack2(acc1);
    const float2 f2 = unpack2(acc2), f3 = unpack2(acc3);
    float s = fmaf(a0x, f0.x, fmaf(a1x, f1.x, fmaf(a2x, f2.x, a3x * f3.x)))
            + fmaf(a0y, f0.y, fmaf(a1y, f1.y, fmaf(a2y, f2.y, a3y * f3.y)));
    if (!diag) s = s + s;
    else if (chunk == 0) {
        const float qq = fmaf(a0x, a0x, fmaf(a1x, a1x, fmaf(a2x, a2x, a3x * a3x)))
                       + fmaf(a0y, a0y, fmaf(a1y, a1y, fmaf(a2y, a2y, a3y * a3y)));
        s = fmaf(SELF_RATIO, qq, s);
    }

    // deterministic in-block reduction (8 warps)
#pragma unroll
    for (int o = 16; o > 0; o >>= 1)
        s += __shfl_down_sync(0xffffffffu, s, o);

    __shared__ float red[TPB / 32];
    if ((t & 31) == 0) red[t >> 5] = s;
    __syncthreads();

    __shared__ bool is_last;
    if (t == 0) {
        g_partials[blockIdx.x] = ((red[0] + red[1]) + (red[2] + red[3]))
                               + ((red[4] + red[5]) + (red[6] + red[7]));
        __threadfence();
        const unsigned int c = atomicAdd(&g_count, 1u);
        is_last = (c == NBLK - 1);
    }
    __syncthreads();

    // last CTA: fixed-order fp64 final reduction + scale
    if (is_last) {
        __threadfence();
        double d = (double)g_partials[t] + (double)g_partials[t + 256];
        if (t < NBLK - 512) d += (double)g_partials[t + 512];

        __shared__ double rs[TPB];
        rs[t] = d;
        __syncthreads();
#pragma unroll
        for (int o = TPB / 2; o > 0; o >>= 1) {
            if (t < o) rs[t] += rs[t + o];
            __syncthreads();
        }
        if (t == 0) {
            const double INV_4PI = 0.07957747154594767;
            out[0] = (float)(rs[0] * INV_4PI);
            g_count = 0;   // reset for next graph replay
        }
    }
}

extern "C" void kernel_launch(void* const* d_in, const int* in_sizes, int n_in,
                              void* d_out, int out_size) {
    const float* pos = (const float*)d_in[0];   // [8192,3] fp32
    const float* q   = (const float*)d_in[1];   // [8192,4] fp32
    float* out = (float*)d_out;                 // [1] fp32

    ewald_pair_kernel<<<NBLK, TPB>>>(pos, q, out);
}